// round 9
// baseline (speedup 1.0000x reference)
#include <cuda_runtime.h>
#include <cstdint>

// Problem dims (fixed)
#define Bv 64
#define Hv 128
#define Wv 128
#define Cv 3
#define Nv 10

#define ROWS 16                // output rows per CTA
#define SRR (ROWS + 4)         // 20 strip rows
#define PXB 64                 // pixels (width) per CTA
#define SCV (PXB + 4)          // 68 valid strip cols
#define SST 76                 // strip row stride (76 % 32 = 12, conflict-free)
#define PLSTRIDE 1547          // per-channel plane stride (mod 32 = 11)
#define NT 128                 // 4 warps, one 16-px col tile each

__device__ __forceinline__ uint32_t to_tf32(float v) {
    uint32_t u;
    asm("cvt.rna.tf32.f32 %0, %1;" : "=r"(u) : "f"(v));
    return u;
}

__device__ __forceinline__ void mma_tf32(float c[4], const uint32_t a[4],
                                         uint32_t b0, uint32_t b1) {
    asm("mma.sync.aligned.m16n8k8.row.col.f32.tf32.tf32.f32 "
        "{%0,%1,%2,%3}, {%4,%5,%6,%7}, {%8,%9}, {%0,%1,%2,%3};"
        : "+f"(c[0]), "+f"(c[1]), "+f"(c[2]), "+f"(c[3])
        : "r"(a[0]), "r"(a[1]), "r"(a[2]), "r"(a[3]), "r"(b0), "r"(b1));
}

// out[n][b][c][h][w] = sum_{kh,kw} images[b][h+kh-2][w+kw-2][c] * kernels[b][kh][kw][n]
// K laid out kh-major (k = 8*kh + kw, kw slots 5..7 zero): one strip-row fragment
// serves all 5 kh groups. One CTA = all 3 channels (coalesced staging, shared W).
__global__ __launch_bounds__(NT, 5)
void cdna_mma_kernel(const float* __restrict__ images,
                     const float* __restrict__ kernels,
                     float* __restrict__ out)
{
    __shared__ float strip[Cv * PLSTRIDE];   // tf32-rounded strips, one plane per c
    __shared__ float Wsm[40][16];            // tf32-rounded weights [k=8kh+kw][n]

    const int tid  = threadIdx.x;
    const int lane = tid & 31;
    const int wrp  = tid >> 5;         // 0..3: 16-px column tile
    const int g    = lane >> 2;        // 0..7
    const int tg   = lane & 3;         // 0..3
    const bool t24 = (tg == 0);

    const int bx = blockIdx.x & 1;     // width half
    const int rt = blockIdx.x >> 1;    // row tile 0..7
    const int b  = blockIdx.z;
    const int r0 = rt * ROWS;
    const int px0 = bx * PXB;

    // ---- stage W: [k=40][n=16], kh-major slots, tf32-rounded, pad -> 0 ----
    for (int i = tid; i < 640; i += NT) {
        int k = i >> 4, n = i & 15;
        int s = k >> 3, t = k & 7;
        float v = 0.0f;
        if (t < 5 && n < Nv) v = kernels[(b * 25 + s * 5 + t) * Nv + n];
        Wsm[k][n] = __uint_as_float(to_tf32(v));
    }

    // ---- stage all-channel strip, coalesced ((pix,c) interleaved in gmem) ----
    const float* imgb = images + (size_t)b * Hv * Wv * Cv;
    for (int i = tid; i < SRR * SCV * Cv; i += NT) {
        int r   = i / (SCV * Cv);
        int rem = i - r * (SCV * Cv);
        int cc  = rem / Cv;
        int ch  = rem - cc * Cv;
        int gh = r0 + r - 2;
        int gw = px0 + cc - 2;
        float v = 0.0f;
        if (gh >= 0 && gh < Hv && gw >= 0 && gw < Wv)
            v = imgb[(gh * Wv + gw) * Cv + ch];
        strip[ch * PLSTRIDE + r * SST + cc] = __uint_as_float(to_tf32(v));
    }
    __syncthreads();

    // ---- B fragments: bf[s=kh][u][j]  (shared by all 3 channels) ----
    uint32_t bf[5][2][2];
    #pragma unroll
    for (int s = 0; s < 5; s++)
        #pragma unroll
        for (int u = 0; u < 2; u++) {
            bf[s][u][0] = __float_as_uint(Wsm[8 * s + tg][8 * u + g]);
            bf[s][u][1] = __float_as_uint(Wsm[8 * s + tg + 4][8 * u + g]);
        }

    const int x = wrp * 16 + g;        // A-row m=g pixel (m=g+8 -> x+8)
    const size_t ns = (size_t)Bv * Cv * Hv * Wv;

    #pragma unroll 1
    for (int ch = 0; ch < Cv; ch++) {
        const float* splane = strip + ch * PLSTRIDE + x;
        float* outbc = out + (((size_t)b * Cv + ch) * Hv + r0) * Wv + px0;

        float acc[5][2][4] = {};

        // prefetch fragment for row 0
        uint32_t a[4];
        {
            const float* sr = splane;
            a[0] = __float_as_uint(sr[tg]);
            a[1] = __float_as_uint(sr[8 + tg]);
            a[2] = t24 ? __float_as_uint(sr[4]) : 0u;
            a[3] = t24 ? __float_as_uint(sr[12]) : 0u;
        }

        #pragma unroll
        for (int ai = 0; ai < SRR; ai++) {
            uint32_t an[4];
            if (ai + 1 < SRR) {        // prefetch next row's fragment
                const float* sr = splane + (ai + 1) * SST;
                an[0] = __float_as_uint(sr[tg]);
                an[1] = __float_as_uint(sr[8 + tg]);
                an[2] = t24 ? __float_as_uint(sr[4]) : 0u;
                an[3] = t24 ? __float_as_uint(sr[12]) : 0u;
            }

            #pragma unroll
            for (int s = 0; s < 5; s++) {
                const int r = ai - s;
                if (r >= 0 && r < ROWS) {
                    const int sl = r % 5;
                    mma_tf32(acc[sl][0], a, bf[s][0][0], bf[s][0][1]);
                    mma_tf32(acc[sl][1], a, bf[s][1][0], bf[s][1][1]);
                }
            }

            const int rd = ai - 4;      // completed output row
            if (rd >= 0) {
                const int sl = rd % 5;
                float* orow = outbc + (size_t)rd * Wv + wrp * 16 + g;
                orow[(size_t)(2 * tg)     * ns]     = acc[sl][0][0];
                orow[(size_t)(2 * tg + 1) * ns]     = acc[sl][0][1];
                orow[(size_t)(2 * tg)     * ns + 8] = acc[sl][0][2];
                orow[(size_t)(2 * tg + 1) * ns + 8] = acc[sl][0][3];
                if (t24) {               // n = 8, 9
                    orow[8 * ns]     = acc[sl][1][0];
                    orow[9 * ns]     = acc[sl][1][1];
                    orow[8 * ns + 8] = acc[sl][1][2];
                    orow[9 * ns + 8] = acc[sl][1][3];
                }
                #pragma unroll
                for (int u = 0; u < 2; u++)
                    #pragma unroll
                    for (int q = 0; q < 4; q++)
                        acc[sl][u][q] = 0.0f;
            }

            a[0] = an[0]; a[1] = an[1]; a[2] = an[2]; a[3] = an[3];
        }
    }
}

extern "C" void kernel_launch(void* const* d_in, const int* in_sizes, int n_in,
                              void* d_out, int out_size)
{
    const float* images  = (const float*)d_in[0];   // [B,H,W,C]
    const float* kernels = (const float*)d_in[1];   // [B,KH,KW,N]
    float* out = (float*)d_out;                     // [N,B,C,H,W]

    dim3 block(NT, 1, 1);
    dim3 grid((Wv / PXB) * (Hv / ROWS), 1, Bv);   // (16, 1, 64) = 1024 CTAs
    cdna_mma_kernel<<<grid, block>>>(images, kernels, out);
}

// round 10
// speedup vs baseline: 1.1665x; 1.1665x over previous
#include <cuda_runtime.h>
#include <cstdint>

// Problem dims (fixed)
#define Bv 64
#define Hv 128
#define Wv 128
#define Cv 3
#define Nv 10

#define ROWS 32                // output rows per CTA
#define SRR (ROWS + 4)         // 36 strip rows
#define PXB 64                 // pixels (width) per CTA
#define SCV (PXB + 4)          // 68 valid strip cols
#define SST 76                 // padded strip stride (76 % 32 = 12, conflict-free)
#define NT 128                 // 4 warps, one 16-px col tile each

__device__ __forceinline__ uint32_t to_tf32(float v) {
    uint32_t u;
    asm("cvt.rna.tf32.f32 %0, %1;" : "=r"(u) : "f"(v));
    return u;
}

__device__ __forceinline__ void mma_tf32(float c[4], const uint32_t a[4],
                                         uint32_t b0, uint32_t b1) {
    asm("mma.sync.aligned.m16n8k8.row.col.f32.tf32.tf32.f32 "
        "{%0,%1,%2,%3}, {%4,%5,%6,%7}, {%8,%9}, {%0,%1,%2,%3};"
        : "+f"(c[0]), "+f"(c[1]), "+f"(c[2]), "+f"(c[3])
        : "r"(a[0]), "r"(a[1]), "r"(a[2]), "r"(a[3]), "r"(b0), "r"(b1));
}

// out[n][b][c][h][w] = sum_{kh,kw} images[b][h+kh-2][w+kw-2][c] * kernels[b][kh][kw][n]
// K laid out kh-major: k = 8*kh + kw (kw slots 5..7 zero). One strip-row fragment
// serves all 5 kh-groups (for output rows ai-0 .. ai-4) -> 4 LDS feed 10 MMAs.
// Fragment for row ai+1 is prefetched before row ai's MMA burst.
__global__ __launch_bounds__(NT, 5)
void cdna_mma_kernel(const float* __restrict__ images,
                     const float* __restrict__ kernels,
                     float* __restrict__ out)
{
    __shared__ float strip[SRR * SST];   // tf32-rounded image strip
    __shared__ float Wsm[40][16];        // tf32-rounded weights [k=8kh+kw][n]

    const int tid  = threadIdx.x;
    const int lane = tid & 31;
    const int wrp  = tid >> 5;         // 0..3: 16-px column tile
    const int g    = lane >> 2;        // 0..7
    const int tg   = lane & 3;         // 0..3
    const bool t24 = (tg == 0);

    const int bx = blockIdx.x & 1;     // width half
    const int rt = blockIdx.x >> 1;    // row tile 0..3
    const int c  = blockIdx.y;
    const int b  = blockIdx.z;
    const int r0 = rt * ROWS;
    const int px0 = bx * PXB;

    // ---- stage W: [k=40][n=16], kh-major slots, tf32-rounded, pad -> 0 ----
    for (int i = tid; i < 640; i += NT) {
        int k = i >> 4, n = i & 15;
        int s = k >> 3, t = k & 7;
        float v = 0.0f;
        if (t < 5 && n < Nv) v = kernels[(b * 25 + s * 5 + t) * Nv + n];
        Wsm[k][n] = __uint_as_float(to_tf32(v));
    }

    // ---- stage image strip (tf32-rounded, zero-padded halo) ----
    const float* imgb = images + ((size_t)b * Hv) * (Wv * Cv) + c;
    #pragma unroll
    for (int it = 0; it < (SRR * SCV + NT - 1) / NT; it++) {
        int i = it * NT + tid;
        if (i < SRR * SCV) {
            int r  = i / SCV;
            int cc = i - r * SCV;
            int gh = r0 + r - 2;
            int gw = px0 + cc - 2;
            float v = 0.0f;
            if (gh >= 0 && gh < Hv && gw >= 0 && gw < Wv)
                v = imgb[(gh * Wv + gw) * Cv];
            strip[r * SST + cc] = __uint_as_float(to_tf32(v));
        }
    }
    __syncthreads();

    // ---- B fragments: bf[s=kh][u][j] ----
    uint32_t bf[5][2][2];
    #pragma unroll
    for (int s = 0; s < 5; s++)
        #pragma unroll
        for (int u = 0; u < 2; u++) {
            bf[s][u][0] = __float_as_uint(Wsm[8 * s + tg][8 * u + g]);
            bf[s][u][1] = __float_as_uint(Wsm[8 * s + tg + 4][8 * u + g]);
        }

    const int x = wrp * 16 + g;        // A-row m=g pixel (m=g+8 -> x+8)
    const size_t ns = (size_t)Bv * Cv * Hv * Wv;
    float* outbc = out + (((size_t)b * Cv + c) * Hv + r0) * Wv + px0;

    // ---- 5-row accumulator ring; walk 36 strip rows, prefetch depth 1 ----
    float acc[5][2][4] = {};

    uint32_t a[4];
    {   // fragment for strip row 0
        const float* sr = strip + x;
        a[0] = __float_as_uint(sr[tg]);
        a[1] = __float_as_uint(sr[8 + tg]);
        a[2] = t24 ? __float_as_uint(sr[4]) : 0u;
        a[3] = t24 ? __float_as_uint(sr[12]) : 0u;
    }

    #pragma unroll
    for (int ai = 0; ai < SRR; ai++) {
        uint32_t an[4] = {0u, 0u, 0u, 0u};
        if (ai + 1 < SRR) {            // prefetch next row's fragment
            const float* sr = strip + (ai + 1) * SST + x;
            an[0] = __float_as_uint(sr[tg]);
            an[1] = __float_as_uint(sr[8 + tg]);
            an[2] = t24 ? __float_as_uint(sr[4]) : 0u;
            an[3] = t24 ? __float_as_uint(sr[12]) : 0u;
        }

        #pragma unroll
        for (int s = 0; s < 5; s++) {
            const int r = ai - s;
            if (r >= 0 && r < ROWS) {
                const int sl = r % 5;
                mma_tf32(acc[sl][0], a, bf[s][0][0], bf[s][0][1]);
                mma_tf32(acc[sl][1], a, bf[s][1][0], bf[s][1][1]);
            }
        }

        const int rd = ai - 4;          // completed output row
        if (rd >= 0) {
            const int sl = rd % 5;
            float* orow = outbc + (size_t)rd * Wv + wrp * 16 + g;
            orow[(size_t)(2 * tg)     * ns]     = acc[sl][0][0];
            orow[(size_t)(2 * tg + 1) * ns]     = acc[sl][0][1];
            orow[(size_t)(2 * tg)     * ns + 8] = acc[sl][0][2];
            orow[(size_t)(2 * tg + 1) * ns + 8] = acc[sl][0][3];
            if (t24) {                   // n = 8, 9
                orow[8 * ns]     = acc[sl][1][0];
                orow[9 * ns]     = acc[sl][1][1];
                orow[8 * ns + 8] = acc[sl][1][2];
                orow[9 * ns + 8] = acc[sl][1][3];
            }
            #pragma unroll
            for (int u = 0; u < 2; u++)
                #pragma unroll
                for (int q = 0; q < 4; q++)
                    acc[sl][u][q] = 0.0f;
        }

        a[0] = an[0]; a[1] = an[1]; a[2] = an[2]; a[3] = an[3];
    }
}

extern "C" void kernel_launch(void* const* d_in, const int* in_sizes, int n_in,
                              void* d_out, int out_size)
{
    const float* images  = (const float*)d_in[0];   // [B,H,W,C]
    const float* kernels = (const float*)d_in[1];   // [B,KH,KW,N]
    float* out = (float*)d_out;                     // [N,B,C,H,W]

    dim3 block(NT, 1, 1);
    dim3 grid((Wv / PXB) * (Hv / ROWS), Cv, Bv);   // (8, 3, 64)
    cdna_mma_kernel<<<grid, block>>>(images, kernels, out);
}